// round 11
// baseline (speedup 1.0000x reference)
#include <cuda_runtime.h>
#include <cuda_fp16.h>
#include <cstdint>

// O = softmax(Q K^T / 16) V,  N=M=8192, D=DV=256, fp32 in/out.
// fp16 m16n8k16 mma.sync flash kernel. R11: 512 threads/CTA (16 warps, 4 per
// SMSP -> 2x latency hiding vs R10), same BM=64/BN=32 tiling so per-SM work
// and L2 traffic are unchanged. QK warp = 16 rows x 8 keys; PV warp = 16-col
// band. Strides 132/20/20 conflict-free for their access patterns.

#define NQ   8192
#define NKV  8192
#define DIM  256
#define DVD  256
#define BM   64
#define BN   32
#define NSPLIT 8
#define KVPER (NKV / NSPLIT)     // 1024
#define TILESU (KVPER / BN)      // 32
#define NT   512

#define KSTR 132                 // K tile row stride (words), 132 % 32 = 4
#define VSTR 20                  // Vt row stride (words), 20 % 32 = 20
#define PSTR 20                  // P row stride
#define KT_WORDS (BN * KSTR)     // 4224
#define VT_WORDS (DVD * VSTR)    // 5120
#define SMEM_WORDS (2 * KT_WORDS + 2 * VT_WORDS + BM * PSTR + 4 * BM)
#define SMEM_BYTES (SMEM_WORDS * 4)   // ~80.2 KB

// prescale = (1/sqrt(256)) * log2(e): scores in log2 domain -> ex2
#define QSCALE 0.09016844f

__device__ uint4     g_Qfrag[NQ * DIM / 8];        // fp16 A-frag order
__device__ uint32_t  g_Kh[NKV * DIM / 2];          // fp16 K row-major
__device__ uint32_t  g_Vth[(NKV / BN) * DVD * (BN / 2)];  // fp16 V^T per-tile [256][16]
__device__ float     g_Opart[(size_t)NSPLIT * NQ * DVD];
__device__ float     g_Lpart[NSPLIT * NQ];

__device__ __forceinline__ float ex2f(float x) {
    float y; asm("ex2.approx.ftz.f32 %0, %1;" : "=f"(y) : "f"(x)); return y;
}
__device__ __forceinline__ uint32_t packh2(float lo, float hi) {
    __half2 h = __floats2half2_rn(lo, hi);
    return *(uint32_t*)&h;
}
__device__ __forceinline__ void mma_f16(float& c0, float& c1, float& c2, float& c3,
                                        uint32_t a0, uint32_t a1, uint32_t a2, uint32_t a3,
                                        uint32_t b0, uint32_t b1) {
    asm volatile(
        "mma.sync.aligned.m16n8k16.row.col.f32.f16.f16.f32 "
        "{%0,%1,%2,%3}, {%4,%5,%6,%7}, {%8,%9}, {%0,%1,%2,%3};"
        : "+f"(c0), "+f"(c1), "+f"(c2), "+f"(c3)
        : "r"(a0), "r"(a1), "r"(a2), "r"(a3), "r"(b0), "r"(b1));
}
__device__ __forceinline__ void cpa16(uint32_t dst_smem, const void* src) {
    asm volatile("cp.async.cg.shared.global [%0], [%1], 16;" :: "r"(dst_smem), "l"(src));
}
#define CP_COMMIT() asm volatile("cp.async.commit_group;" ::: "memory")
#define CP_WAIT0()  asm volatile("cp.async.wait_group 0;" ::: "memory")

// K tile: [32 keys x 128 words] -> smem stride KSTR. 1024 chunks, 2/thread.
__device__ __forceinline__ void ldKtile(uint32_t base, const uint32_t* __restrict__ src,
                                        int tid) {
#pragma unroll
    for (int j = 0; j < 2; j++) {
        int f = tid + j * NT;
        int row = f >> 5, c = (f & 31) << 2;
        cpa16(base + (uint32_t)(row * KSTR + c) * 4u, src + row * (DIM / 2) + c);
    }
}
// Vt tile: [256 d x 16 words] -> smem stride VSTR. 1024 chunks, 2/thread.
__device__ __forceinline__ void ldVtile(uint32_t base, const uint32_t* __restrict__ src,
                                        int tid) {
#pragma unroll
    for (int j = 0; j < 2; j++) {
        int f = tid + j * NT;
        int d = f >> 2, s = (f & 3) << 2;
        cpa16(base + (uint32_t)(d * VSTR + s) * 4u, src + d * (BN / 2) + s);
    }
}

// ---- prepass: K -> fp16 row-major ----
__global__ void __launch_bounds__(256)
cvtK_kernel(const float4* __restrict__ K) {
    int i = blockIdx.x * 256 + threadIdx.x;
    float4 k = K[i];
    uint2 o;
    o.x = packh2(k.x, k.y);
    o.y = packh2(k.z, k.w);
    ((uint2*)g_Kh)[i] = o;
}

// ---- prepass: Q * QSCALE -> fp16, m16n8k16 A-fragment order ----
// word w: j=w&3, kk=(w>>2)&15, lane=(w>>6)&31, rblk=w>>11
// row = rblk*16 + (j&1)*8 + (lane>>2),  col = kk*16 + (j>>1)*8 + 2*(lane&3)
__global__ void __launch_bounds__(256)
repackQ_kernel(const float* __restrict__ Q) {
    int w = blockIdx.x * 256 + threadIdx.x;
    int j    = w & 3;
    int kk   = (w >> 2) & 15;
    int lane = (w >> 6) & 31;
    int rblk = w >> 11;
    int row = rblk * 16 + (j & 1) * 8 + (lane >> 2);
    int col = kk * 16 + (j >> 1) * 8 + 2 * (lane & 3);
    const float* src = Q + (size_t)row * DIM + col;
    ((uint32_t*)g_Qfrag)[w] = packh2(src[0] * QSCALE, src[1] * QSCALE);
}

// ---- prepass: V -> fp16 V^T, tile-contiguous [tile][256 d][16 words] ----
__global__ void __launch_bounds__(256)
transpV_kernel(const float* __restrict__ V) {
    __shared__ float t[32][33];
    int tile = blockIdx.x;
    int d0   = blockIdx.y * 32;
    int tx = threadIdx.x & 31, ty = threadIdx.x >> 5;
    int m0 = tile * 32;
#pragma unroll
    for (int j = 0; j < 4; j++)
        t[ty + 8 * j][tx] = V[(size_t)(m0 + ty + 8 * j) * DVD + d0 + tx];
    __syncthreads();
#pragma unroll
    for (int jj = 0; jj < 2; jj++) {
        int w = threadIdx.x + 256 * jj;       // 0..511
        int dloc = w >> 4;
        int kw   = w & 15;
        g_Vth[(size_t)tile * (DVD * BN / 2) + (d0 + dloc) * (BN / 2) + kw] =
            packh2(t[2 * kw][dloc], t[2 * kw + 1][dloc]);
    }
}

// ---- main attention kernel: grid = (NQ/BM) * NSPLIT = 1024 CTAs ----
__global__ void __launch_bounds__(NT, 1)
attn_kernel() {
    extern __shared__ uint32_t sm[];
    uint32_t* kb   = sm;                               // [2][BN][KSTR]
    uint32_t* vb   = sm + 2 * KT_WORDS;                // [2][DVD][VSTR]
    uint32_t* pbm  = sm + 2 * KT_WORDS + 2 * VT_WORDS; // [BM][PSTR]
    float*    lred = (float*)(pbm + BM * PSTR);        // [BM][4]

    const int tid  = threadIdx.x;
    const int lane = tid & 31;
    const int warp = tid >> 5;
    const int r = warp & 3;       // QK: 16-row group
    const int h = warp >> 2;      // QK: key octet (8 keys)
    const int g = lane >> 2;
    const int t = lane & 3;

    const int qt    = blockIdx.x >> 3;
    const int split = blockIdx.x & 7;

    uint32_t smb  = (uint32_t)__cvta_generic_to_shared(sm);
    uint32_t kb_b = smb;
    uint32_t vb_b = smb + 2u * KT_WORDS * 4u;

    const uint32_t* Kg = g_Kh + (size_t)split * KVPER * (DIM / 2);
    const uint32_t* Vg = g_Vth + (size_t)(split * TILESU) * (DVD * BN / 2);

    // prologue: tile 0 into buffer 0
    ldKtile(kb_b, Kg, tid);
    ldVtile(vb_b, Vg, tid);
    CP_COMMIT();

    // Q A-fragments (coalesced uint4 loads from fragment-order scratch)
    uint32_t qa[16][4];
    {
        const uint4* qf = g_Qfrag + ((size_t)(qt * 4 + r) * 32 + lane) * 16;
#pragma unroll
        for (int kk = 0; kk < 16; kk++) {
            uint4 v = qf[kk];
            qa[kk][0] = v.x; qa[kk][1] = v.y; qa[kk][2] = v.z; qa[kk][3] = v.w;
        }
    }

    float o[8][4];
#pragma unroll
    for (int n = 0; n < 8; n++) { o[n][0] = o[n][1] = o[n][2] = o[n][3] = 0.f; }
    float ls0 = 0.f, ls1 = 0.f;
    const int row0 = 16 * r + g;

    for (int i = 0; i < TILESU; i++) {
        CP_WAIT0();
        __syncthreads();   // tile i visible; all warps done with tile i-1 and P

        if (i + 1 < TILESU) {
            uint32_t bofs = (uint32_t)((i + 1) & 1);
            ldKtile(kb_b + bofs * KT_WORDS * 4u, Kg + (size_t)(i + 1) * BN * (DIM / 2), tid);
            ldVtile(vb_b + bofs * VT_WORDS * 4u, Vg + (size_t)(i + 1) * (DVD * BN / 2), tid);
            CP_COMMIT();
        }

        // ---- S = Q K^T for warp's [16 rows x 8 keys] ----
        const uint32_t* kr = kb + (i & 1) * KT_WORDS + (8 * h + g) * KSTR + t;
        float sc0 = 0.f, sc1 = 0.f, sc2 = 0.f, sc3 = 0.f;
#pragma unroll
        for (int kk = 0; kk < 16; kk++) {
            uint32_t b0 = kr[kk * 8], b1 = kr[kk * 8 + 4];
            mma_f16(sc0, sc1, sc2, sc3,
                    qa[kk][0], qa[kk][1], qa[kk][2], qa[kk][3], b0, b1);
        }

        // ---- P = 2^S, accumulate row sums, P -> smem (fp16x2) ----
        {
            float p0 = ex2f(sc0), p1 = ex2f(sc1), p2 = ex2f(sc2), p3 = ex2f(sc3);
            ls0 += p0 + p1;
            ls1 += p2 + p3;
            int wcol = 4 * h + t;
            pbm[row0 * PSTR + wcol]       = packh2(p0, p1);
            pbm[(row0 + 8) * PSTR + wcol] = packh2(p2, p3);
        }
        __syncthreads();   // full P tile visible

        // ---- O += P V: warp = one 16-col d band, all 64 rows ----
        const uint32_t* vbp = vb + (i & 1) * VT_WORDS;
#pragma unroll
        for (int kk = 0; kk < 2; kk++) {
            uint32_t a[4][4];
#pragma unroll
            for (int rg = 0; rg < 4; rg++) {
                const uint32_t* pr = pbm + (16 * rg + g) * PSTR + kk * 8 + t;
                a[rg][0] = pr[0];
                a[rg][1] = pr[8 * PSTR];
                a[rg][2] = pr[4];
                a[rg][3] = pr[8 * PSTR + 4];
            }
#pragma unroll
            for (int j = 0; j < 2; j++) {
                const uint32_t* vr = vbp + (warp * 16 + j * 8 + g) * VSTR + kk * 8 + t;
                uint32_t b0 = vr[0], b1 = vr[4];
#pragma unroll
                for (int rg = 0; rg < 4; rg++)
                    mma_f16(o[rg * 2 + j][0], o[rg * 2 + j][1],
                            o[rg * 2 + j][2], o[rg * 2 + j][3],
                            a[rg][0], a[rg][1], a[rg][2], a[rg][3], b0, b1);
            }
        }
    }

    // ---- epilogue: row sums across 4 key-octet warps, write partials ----
    ls0 += __shfl_xor_sync(0xffffffffu, ls0, 1);
    ls0 += __shfl_xor_sync(0xffffffffu, ls0, 2);
    ls1 += __shfl_xor_sync(0xffffffffu, ls1, 1);
    ls1 += __shfl_xor_sync(0xffffffffu, ls1, 2);
    if (t == 0) {
        lred[(row0)     * 4 + h] = ls0;
        lred[(row0 + 8) * 4 + h] = ls1;
    }
    __syncthreads();
    if (tid < BM)
        g_Lpart[split * NQ + qt * BM + tid] =
            lred[tid * 4] + lred[tid * 4 + 1] + lred[tid * 4 + 2] + lred[tid * 4 + 3];

    float* ob = g_Opart + ((size_t)split * NQ + (size_t)qt * BM) * DVD;
#pragma unroll
    for (int rg = 0; rg < 4; rg++) {
#pragma unroll
        for (int j = 0; j < 2; j++) {
            int col  = warp * 16 + j * 8 + 2 * t;
            int rowA = 16 * rg + g;
            *(float2*)(ob + (size_t)rowA * DVD + col) =
                make_float2(o[rg * 2 + j][0], o[rg * 2 + j][1]);
            *(float2*)(ob + (size_t)(rowA + 8) * DVD + col) =
                make_float2(o[rg * 2 + j][2], o[rg * 2 + j][3]);
        }
    }
}

// ---- combine split partials ----
__global__ void __launch_bounds__(256)
combine_kernel(float* __restrict__ out) {
    int i = blockIdx.x * 256 + threadIdx.x;
    int row = i >> 8;
    float num = 0.f, den = 0.f;
#pragma unroll
    for (int s = 0; s < NSPLIT; s++) {
        num += g_Opart[(size_t)s * NQ * DVD + i];
        den += g_Lpart[s * NQ + row];
    }
    out[i] = num / den;
}

extern "C" void kernel_launch(void* const* d_in, const int* in_sizes, int n_in,
                              void* d_out, int out_size) {
    const float* q = (const float*)d_in[0];
    const float* k = (const float*)d_in[1];
    const float* v = (const float*)d_in[2];
    float* out = (float*)d_out;
    (void)in_sizes; (void)n_in; (void)out_size;

    cvtK_kernel<<<NKV * DIM / 4 / 256, 256>>>((const float4*)k);
    repackQ_kernel<<<NQ * DIM / 2 / 256, 256>>>(q);
    transpV_kernel<<<dim3(NKV / 32, DVD / 32), 256>>>(v);

    cudaFuncSetAttribute(attn_kernel,
                         cudaFuncAttributeMaxDynamicSharedMemorySize, SMEM_BYTES);
    attn_kernel<<<(NQ / BM) * NSPLIT, NT, SMEM_BYTES>>>();

    combine_kernel<<<NQ * DVD / 256, 256>>>(out);
}

// round 13
// speedup vs baseline: 1.0894x; 1.0894x over previous
#include <cuda_runtime.h>
#include <cuda_fp16.h>
#include <cstdint>

// O = softmax(Q K^T / 16) V,  N=M=8192, D=DV=256, fp32 in/out.
// fp16 m16n8k16 mma.sync flash kernel. R12: software-pipelined tiles —
// QK(i) interleaved with PV(i-1) in ONE tensor block per tile, P double-
// buffered, V triple-buffered, exactly one __syncthreads per tile (phase
// serialization was the R10/R11 bottleneck). 8 warps / 256 threads (R10
// layout, which beat 16 warps).

#define NQ   8192
#define NKV  8192
#define DIM  256
#define DVD  256
#define BM   64
#define BN   32
#define NSPLIT 8
#define KVPER (NKV / NSPLIT)     // 1024
#define TILESU (KVPER / BN)      // 32
#define NT   256

#define KSTR 132                 // K row stride (words), 4 mod 32: 4g+t distinct
#define VSTR 20                  // V^T row stride, 20 mod 32: 20g+t distinct
#define PSTR 20                  // P row stride
#define KT_WORDS (BN * KSTR)     // 4224
#define VT_WORDS (DVD * VSTR)    // 5120
#define PB_WORDS (BM * PSTR)     // 1280
#define SMEM_WORDS (2 * KT_WORDS + 3 * VT_WORDS + 2 * PB_WORDS + 2 * BM)
#define SMEM_BYTES (SMEM_WORDS * 4)   // 105984

// prescale = (1/sqrt(256)) * log2(e): scores in log2 domain -> ex2
#define QSCALE 0.09016844f

__device__ uint4     g_Qfrag[NQ * DIM / 8];        // fp16 A-frag order
__device__ uint32_t  g_Kh[NKV * DIM / 2];          // fp16 K row-major
__device__ uint32_t  g_Vth[(NKV / BN) * DVD * (BN / 2)];  // fp16 V^T per-tile [256][16]
__device__ float     g_Opart[(size_t)NSPLIT * NQ * DVD];
__device__ float     g_Lpart[NSPLIT * NQ];

__device__ __forceinline__ float ex2f(float x) {
    float y; asm("ex2.approx.ftz.f32 %0, %1;" : "=f"(y) : "f"(x)); return y;
}
__device__ __forceinline__ uint32_t packh2(float lo, float hi) {
    __half2 h = __floats2half2_rn(lo, hi);
    return *(uint32_t*)&h;
}
__device__ __forceinline__ void mma_f16(float& c0, float& c1, float& c2, float& c3,
                                        uint32_t a0, uint32_t a1, uint32_t a2, uint32_t a3,
                                        uint32_t b0, uint32_t b1) {
    asm volatile(
        "mma.sync.aligned.m16n8k16.row.col.f32.f16.f16.f32 "
        "{%0,%1,%2,%3}, {%4,%5,%6,%7}, {%8,%9}, {%0,%1,%2,%3};"
        : "+f"(c0), "+f"(c1), "+f"(c2), "+f"(c3)
        : "r"(a0), "r"(a1), "r"(a2), "r"(a3), "r"(b0), "r"(b1));
}
__device__ __forceinline__ void cpa16(uint32_t dst_smem, const void* src) {
    asm volatile("cp.async.cg.shared.global [%0], [%1], 16;" :: "r"(dst_smem), "l"(src));
}
#define CP_COMMIT() asm volatile("cp.async.commit_group;" ::: "memory")
#define CP_WAIT0()  asm volatile("cp.async.wait_group 0;" ::: "memory")

// K tile: [32 keys x 128 words] -> smem stride KSTR. 1024 chunks, 4/thread.
__device__ __forceinline__ void ldKtile(uint32_t base, const uint32_t* __restrict__ src,
                                        int tid) {
#pragma unroll
    for (int j = 0; j < 4; j++) {
        int f = tid + j * NT;
        int row = f >> 5, c = (f & 31) << 2;
        cpa16(base + (uint32_t)(row * KSTR + c) * 4u, src + row * (DIM / 2) + c);
    }
}
// Vt tile: [256 d x 16 words] -> smem stride VSTR. 1024 chunks, 4/thread.
__device__ __forceinline__ void ldVtile(uint32_t base, const uint32_t* __restrict__ src,
                                        int tid) {
#pragma unroll
    for (int j = 0; j < 4; j++) {
        int f = tid + j * NT;
        int d = f >> 2, s = (f & 3) << 2;
        cpa16(base + (uint32_t)(d * VSTR + s) * 4u, src + d * (BN / 2) + s);
    }
}

// ---- prepass: K -> fp16 row-major ----
__global__ void __launch_bounds__(256)
cvtK_kernel(const float4* __restrict__ K) {
    int i = blockIdx.x * 256 + threadIdx.x;
    float4 k = K[i];
    uint2 o;
    o.x = packh2(k.x, k.y);
    o.y = packh2(k.z, k.w);
    ((uint2*)g_Kh)[i] = o;
}

// ---- prepass: Q * QSCALE -> fp16, m16n8k16 A-fragment order ----
__global__ void __launch_bounds__(256)
repackQ_kernel(const float* __restrict__ Q) {
    int w = blockIdx.x * 256 + threadIdx.x;
    int j    = w & 3;
    int kk   = (w >> 2) & 15;
    int lane = (w >> 6) & 31;
    int rblk = w >> 11;
    int row = rblk * 16 + (j & 1) * 8 + (lane >> 2);
    int col = kk * 16 + (j >> 1) * 8 + 2 * (lane & 3);
    const float* src = Q + (size_t)row * DIM + col;
    ((uint32_t*)g_Qfrag)[w] = packh2(src[0] * QSCALE, src[1] * QSCALE);
}

// ---- prepass: V -> fp16 V^T, tile-contiguous [tile][256 d][16 words] ----
__global__ void __launch_bounds__(256)
transpV_kernel(const float* __restrict__ V) {
    __shared__ float t[32][33];
    int tile = blockIdx.x;
    int d0   = blockIdx.y * 32;
    int tx = threadIdx.x & 31, ty = threadIdx.x >> 5;
    int m0 = tile * 32;
#pragma unroll
    for (int j = 0; j < 4; j++)
        t[ty + 8 * j][tx] = V[(size_t)(m0 + ty + 8 * j) * DVD + d0 + tx];
    __syncthreads();
#pragma unroll
    for (int jj = 0; jj < 2; jj++) {
        int w = threadIdx.x + 256 * jj;
        int dloc = w >> 4;
        int kw   = w & 15;
        g_Vth[(size_t)tile * (DVD * BN / 2) + (d0 + dloc) * (BN / 2) + kw] =
            packh2(t[2 * kw][dloc], t[2 * kw + 1][dloc]);
    }
}

// ---- main attention kernel: grid = (NQ/BM) * NSPLIT = 1024 CTAs ----
__global__ void __launch_bounds__(NT, 1)
attn_kernel() {
    extern __shared__ uint32_t sm[];
    uint32_t* kb   = sm;                                 // [2][BN][KSTR]
    uint32_t* vb   = sm + 2 * KT_WORDS;                  // [3][DVD][VSTR]
    uint32_t* pb   = sm + 2 * KT_WORDS + 3 * VT_WORDS;   // [2][BM][PSTR]
    float*    lred = (float*)(pb + 2 * PB_WORDS);        // [BM][2]

    const int tid  = threadIdx.x;
    const int lane = tid & 31;
    const int warp = tid >> 5;
    const int r = warp & 3;       // QK: 16-row group
    const int h = warp >> 2;      // QK: 16-key half
    const int g = lane >> 2;
    const int t = lane & 3;

    const int qt    = blockIdx.x >> 3;
    const int split = blockIdx.x & 7;

    uint32_t smb  = (uint32_t)__cvta_generic_to_shared(sm);
    uint32_t kb_b = smb;
    uint32_t vb_b = smb + 2u * KT_WORDS * 4u;

    const uint32_t* Kg = g_Kh + (size_t)split * KVPER * (DIM / 2);
    const uint32_t* Vg = g_Vth + (size_t)(split * TILESU) * (DVD * BN / 2);

    // prologue: tile 0 into K buf 0 / V buf 0
    ldKtile(kb_b, Kg, tid);
    ldVtile(vb_b, Vg, tid);
    CP_COMMIT();

    // Q A-fragments
    uint32_t qa[16][4];
    {
        const uint4* qf = g_Qfrag + ((size_t)(qt * 4 + r) * 32 + lane) * 16;
#pragma unroll
        for (int kk = 0; kk < 16; kk++) {
            uint4 v = qf[kk];
            qa[kk][0] = v.x; qa[kk][1] = v.y; qa[kk][2] = v.z; qa[kk][3] = v.w;
        }
    }

    float o[16][4];
#pragma unroll
    for (int n = 0; n < 16; n++) { o[n][0] = o[n][1] = o[n][2] = o[n][3] = 0.f; }
    float ls0 = 0.f, ls1 = 0.f;
    const int row0 = 16 * r + g;

    for (int i = 0; i < TILESU; i++) {
        CP_WAIT0();
        __syncthreads();   // ONE barrier per tile: K(i),V(i) visible; P(i-1) visible;
                           // all reads of K(i-1),V(i-2),P(i-2) complete.

        if (i + 1 < TILESU) {
            ldKtile(kb_b + (uint32_t)((i + 1) & 1) * KT_WORDS * 4u,
                    Kg + (size_t)(i + 1) * BN * (DIM / 2), tid);
            ldVtile(vb_b + (uint32_t)((i + 1) % 3) * VT_WORDS * 4u,
                    Vg + (size_t)(i + 1) * (DVD * BN / 2), tid);
            CP_COMMIT();
        }

        const uint32_t* kr0 = kb + (i & 1) * KT_WORDS + (h * 16 + g) * KSTR + t;
        const uint32_t* kr1 = kr0 + 8 * KSTR;
        float sc[2][4];
        sc[0][0] = sc[0][1] = sc[0][2] = sc[0][3] = 0.f;
        sc[1][0] = sc[1][1] = sc[1][2] = sc[1][3] = 0.f;

        if (i == 0) {
            // plain QK(0)
#pragma unroll
            for (int s = 0; s < 16; s++) {
                uint32_t b00 = kr0[s * 8], b01 = kr0[s * 8 + 4];
                uint32_t b10 = kr1[s * 8], b11 = kr1[s * 8 + 4];
                mma_f16(sc[0][0], sc[0][1], sc[0][2], sc[0][3],
                        qa[s][0], qa[s][1], qa[s][2], qa[s][3], b00, b01);
                mma_f16(sc[1][0], sc[1][1], sc[1][2], sc[1][3],
                        qa[s][0], qa[s][1], qa[s][2], qa[s][3], b10, b11);
            }
        } else {
            // fused: QK(i) interleaved with PV(i-1)
            const uint32_t* vbp = vb + ((i - 1) % 3) * VT_WORDS;
            const uint32_t* pbp = pb + ((i - 1) & 1) * PB_WORDS;
#pragma unroll
            for (int kk2 = 0; kk2 < 2; kk2++) {
                uint32_t vf[4][2];
#pragma unroll
                for (int j = 0; j < 4; j++) {
                    const uint32_t* vr = vbp + (warp * 32 + j * 8 + g) * VSTR + kk2 * 8 + t;
                    vf[j][0] = vr[0];
                    vf[j][1] = vr[4];
                }
#pragma unroll
                for (int rg = 0; rg < 4; rg++) {
                    const uint32_t* pr = pbp + (16 * rg + g) * PSTR + kk2 * 8 + t;
                    uint32_t a0 = pr[0];
                    uint32_t a1 = pr[8 * PSTR];
                    uint32_t a2 = pr[4];
                    uint32_t a3 = pr[8 * PSTR + 4];
                    // two QK k-steps interleaved with this PV chunk
                    const int s0 = kk2 * 8 + rg * 2;
#pragma unroll
                    for (int ss = 0; ss < 2; ss++) {
                        const int s = s0 + ss;
                        uint32_t b00 = kr0[s * 8], b01 = kr0[s * 8 + 4];
                        uint32_t b10 = kr1[s * 8], b11 = kr1[s * 8 + 4];
                        mma_f16(sc[0][0], sc[0][1], sc[0][2], sc[0][3],
                                qa[s][0], qa[s][1], qa[s][2], qa[s][3], b00, b01);
                        mma_f16(sc[1][0], sc[1][1], sc[1][2], sc[1][3],
                                qa[s][0], qa[s][1], qa[s][2], qa[s][3], b10, b11);
                    }
#pragma unroll
                    for (int j = 0; j < 4; j++)
                        mma_f16(o[rg * 4 + j][0], o[rg * 4 + j][1],
                                o[rg * 4 + j][2], o[rg * 4 + j][3],
                                a0, a1, a2, a3, vf[j][0], vf[j][1]);
                }
            }
        }

        // ---- P(i) = 2^S, row sums, store to P buffer i&1 ----
        uint32_t* pbw = pb + (i & 1) * PB_WORDS;
#pragma unroll
        for (int n = 0; n < 2; n++) {
            float p0 = ex2f(sc[n][0]);
            float p1 = ex2f(sc[n][1]);
            float p2 = ex2f(sc[n][2]);
            float p3 = ex2f(sc[n][3]);
            ls0 += p0 + p1;
            ls1 += p2 + p3;
            int wcol = h * 8 + n * 4 + t;
            pbw[row0 * PSTR + wcol]       = packh2(p0, p1);
            pbw[(row0 + 8) * PSTR + wcol] = packh2(p2, p3);
        }
    }

    // ---- tail: PV for last tile ----
    __syncthreads();
    {
        const uint32_t* vbp = vb + ((TILESU - 1) % 3) * VT_WORDS;
        const uint32_t* pbp = pb + ((TILESU - 1) & 1) * PB_WORDS;
#pragma unroll
        for (int kk2 = 0; kk2 < 2; kk2++) {
            uint32_t vf[4][2];
#pragma unroll
            for (int j = 0; j < 4; j++) {
                const uint32_t* vr = vbp + (warp * 32 + j * 8 + g) * VSTR + kk2 * 8 + t;
                vf[j][0] = vr[0];
                vf[j][1] = vr[4];
            }
#pragma unroll
            for (int rg = 0; rg < 4; rg++) {
                const uint32_t* pr = pbp + (16 * rg + g) * PSTR + kk2 * 8 + t;
                uint32_t a0 = pr[0];
                uint32_t a1 = pr[8 * PSTR];
                uint32_t a2 = pr[4];
                uint32_t a3 = pr[8 * PSTR + 4];
#pragma unroll
                for (int j = 0; j < 4; j++)
                    mma_f16(o[rg * 4 + j][0], o[rg * 4 + j][1],
                            o[rg * 4 + j][2], o[rg * 4 + j][3],
                            a0, a1, a2, a3, vf[j][0], vf[j][1]);
            }
        }
    }

    // ---- epilogue: row sums across the 2 key-half warps, write partials ----
    ls0 += __shfl_xor_sync(0xffffffffu, ls0, 1);
    ls0 += __shfl_xor_sync(0xffffffffu, ls0, 2);
    ls1 += __shfl_xor_sync(0xffffffffu, ls1, 1);
    ls1 += __shfl_xor_sync(0xffffffffu, ls1, 2);
    if (t == 0) {
        lred[(row0)     * 2 + h] = ls0;
        lred[(row0 + 8) * 2 + h] = ls1;
    }
    __syncthreads();
    if (tid < BM)
        g_Lpart[split * NQ + qt * BM + tid] = lred[tid * 2] + lred[tid * 2 + 1];

    float* ob = g_Opart + ((size_t)split * NQ + (size_t)qt * BM) * DVD;
#pragma unroll
    for (int rg = 0; rg < 4; rg++) {
#pragma unroll
        for (int j = 0; j < 4; j++) {
            int col  = warp * 32 + j * 8 + 2 * t;
            int rowA = 16 * rg + g;
            *(float2*)(ob + (size_t)rowA * DVD + col) =
                make_float2(o[rg * 4 + j][0], o[rg * 4 + j][1]);
            *(float2*)(ob + (size_t)(rowA + 8) * DVD + col) =
                make_float2(o[rg * 4 + j][2], o[rg * 4 + j][3]);
        }
    }
}

// ---- combine split partials ----
__global__ void __launch_bounds__(256)
combine_kernel(float* __restrict__ out) {
    int i = blockIdx.x * 256 + threadIdx.x;
    int row = i >> 8;
    float num = 0.f, den = 0.f;
#pragma unroll
    for (int s = 0; s < NSPLIT; s++) {
        num += g_Opart[(size_t)s * NQ * DVD + i];
        den += g_Lpart[s * NQ + row];
    }
    out[i] = num / den;
}

extern "C" void kernel_launch(void* const* d_in, const int* in_sizes, int n_in,
                              void* d_out, int out_size) {
    const float* q = (const float*)d_in[0];
    const float* k = (const float*)d_in[1];
    const float* v = (const float*)d_in[2];
    float* out = (float*)d_out;
    (void)in_sizes; (void)n_in; (void)out_size;

    cvtK_kernel<<<NKV * DIM / 4 / 256, 256>>>((const float4*)k);
    repackQ_kernel<<<NQ * DIM / 2 / 256, 256>>>(q);
    transpV_kernel<<<dim3(NKV / 32, DVD / 32), 256>>>(v);

    cudaFuncSetAttribute(attn_kernel,
                         cudaFuncAttributeMaxDynamicSharedMemorySize, SMEM_BYTES);
    attn_kernel<<<(NQ / BM) * NSPLIT, NT, SMEM_BYTES>>>();

    combine_kernel<<<NQ * DVD / 256, 256>>>(out);
}